// round 1
// baseline (speedup 1.0000x reference)
#include <cuda_runtime.h>
#include <math.h>

#define CB_K   1024
#define CH     128
#define NVEC   65536
#define QELEMS 8388608
#define NBLK   1024   // NVEC / 64

// Persistent scratch (no allocations allowed)
__device__ float g_cbT[CH * CB_K];   // transposed codebook [c][k]
__device__ float g_c2[CB_K];         // ||codebook[k]||^2
__device__ float g_partial[NBLK];    // per-block loss partial sums

// ---------------------------------------------------------------------------
// Prep: transpose codebook into [c][k] layout and compute row norms^2.
// One block per code row; coalesced read of the row, scattered (cheap) writes.
// ---------------------------------------------------------------------------
__global__ void prep_kernel(const float* __restrict__ codebook) {
    int k = blockIdx.x;
    int c = threadIdx.x;
    float v = codebook[k * CH + c];
    g_cbT[c * CB_K + k] = v;
    float s = v * v;
    #pragma unroll
    for (int off = 16; off > 0; off >>= 1)
        s += __shfl_down_sync(0xffffffffu, s, off);
    __shared__ float ws[4];
    if ((c & 31) == 0) ws[c >> 5] = s;
    __syncthreads();
    if (c == 0) g_c2[k] = (ws[0] + ws[1]) + (ws[2] + ws[3]);
}

// ---------------------------------------------------------------------------
// Main fused kernel: per block = 64 spatial vectors (one (b,h) row, w=0..63)
//   1) load+transpose x tile -> zsT[c][w]
//   2) per-vector norm -> rn2 = 2/max(nrm,eps), z2 = (nrm*r)^2
//   3) GEMM vs all 1024 codes in 4 tiles of 256, thread tile 4 vec x 16 codes
//      running argmin of  c2[k] - rn2[v]*dotraw[v][k]
//   4) cross-thread argmin reduce (16 lanes), loss = sqrt(z2 + bestE)
//   5) gather chosen codebook rows to SMEM, coalesced write of q
// ---------------------------------------------------------------------------
struct __align__(16) Smem {
    float zsT[CH * 64];     // [c][w], row stride 64 floats (16 float4)
    float cbs[CH * 256];    // [c][code], row stride 256 floats (64 float4); reused as qr[64][129]
    float c2s[256];
    float rn2[64];
    float z2s[64];
    float redsum[16];
    int   sidx[64];
};

__global__ void __launch_bounds__(256, 1)
vq_main(const float* __restrict__ x, const float* __restrict__ codebook,
        float* __restrict__ out) {
    extern __shared__ unsigned char smem_raw[];
    Smem& sm = *reinterpret_cast<Smem*>(smem_raw);

    const int tid = threadIdx.x;
    const int n0  = blockIdx.x * 64;
    const int b   = n0 >> 12;          // n = b*4096 + h*64 + w
    const int h   = (n0 >> 6) & 63;
    const float* xbase = x + (size_t)b * (CH * 4096) + h * 64;

    // ---- load + transpose x tile (coalesced along w) ----
    {
        const int w  = tid & 63;
        const int c0 = tid >> 6;
        #pragma unroll
        for (int it = 0; it < 32; ++it) {
            int c = it * 4 + c0;
            sm.zsT[c * 64 + w] = xbase[c * 4096 + w];
        }
    }
    __syncthreads();

    // ---- per-vector norms (64 threads, conflict-free column reads) ----
    if (tid < 64) {
        float s0 = 0.f, s1 = 0.f, s2 = 0.f, s3 = 0.f;
        #pragma unroll
        for (int c = 0; c < 128; c += 4) {
            float v0 = sm.zsT[(c + 0) * 64 + tid];
            float v1 = sm.zsT[(c + 1) * 64 + tid];
            float v2 = sm.zsT[(c + 2) * 64 + tid];
            float v3 = sm.zsT[(c + 3) * 64 + tid];
            s0 = fmaf(v0, v0, s0); s1 = fmaf(v1, v1, s1);
            s2 = fmaf(v2, v2, s2); s3 = fmaf(v3, v3, s3);
        }
        float s   = (s0 + s1) + (s2 + s3);
        float nrm = sqrtf(s);
        float r   = 1.0f / fmaxf(nrm, 1e-12f);
        sm.rn2[tid] = 2.0f * r;
        sm.z2s[tid] = s * r * r;   // ~1.0, exact per reference semantics
    }

    const int vg = tid >> 4;   // 0..15 : vectors 4*vg .. 4*vg+3
    const int cg = tid & 15;   // 0..15 : code float4-chunks {cg, cg+16, cg+32, cg+48}

    float bestE[4];
    int   bestI[4];
    #pragma unroll
    for (int i = 0; i < 4; ++i) { bestE[i] = 3.4e38f; bestI[i] = 0; }

    const float4* gcb  = reinterpret_cast<const float4*>(g_cbT);
    float4*       cbs4 = reinterpret_cast<float4*>(sm.cbs);
    const float4* zp   = reinterpret_cast<const float4*>(sm.zsT);

    for (int kt = 0; kt < 4; ++kt) {
        __syncthreads();
        // ---- load codebook tile [128 c][256 codes] (coalesced, conflict-free STS) ----
        #pragma unroll
        for (int it = 0; it < 32; ++it) {
            int idx = it * 256 + tid;         // 0..8191 float4s
            int c   = idx >> 6;
            int j4  = idx & 63;
            cbs4[c * 64 + j4] = gcb[c * 256 + kt * 64 + j4];
        }
        sm.c2s[tid] = g_c2[kt * 256 + tid];
        __syncthreads();

        float acc[4][16];
        #pragma unroll
        for (int i = 0; i < 4; ++i)
            #pragma unroll
            for (int j = 0; j < 16; ++j) acc[i][j] = 0.f;

        // ---- 64 FMA per c-step per thread; LDS.128 pattern is bank-conflict-free ----
        #pragma unroll 4
        for (int c = 0; c < 128; ++c) {
            float4 z  = zp[c * 16 + vg];                 // broadcast within half-warp
            float4 q0 = cbs4[c * 64 + cg];               // lanes consecutive -> all banks
            float4 q1 = cbs4[c * 64 + cg + 16];
            float4 q2 = cbs4[c * 64 + cg + 32];
            float4 q3 = cbs4[c * 64 + cg + 48];
            float zz[4]  = { z.x, z.y, z.z, z.w };
            float qq[16] = { q0.x, q0.y, q0.z, q0.w,  q1.x, q1.y, q1.z, q1.w,
                             q2.x, q2.y, q2.z, q2.w,  q3.x, q3.y, q3.z, q3.w };
            #pragma unroll
            for (int i = 0; i < 4; ++i)
                #pragma unroll
                for (int j = 0; j < 16; ++j)
                    acc[i][j] = fmaf(zz[i], qq[j], acc[i][j]);
        }

        // ---- fold normalization + c2, update running argmin (ascending code order) ----
        #pragma unroll
        for (int i = 0; i < 4; ++i) {
            float r2 = sm.rn2[vg * 4 + i];
            #pragma unroll
            for (int m = 0; m < 4; ++m) {
                int colbase = (cg + 16 * m) * 4;
                #pragma unroll
                for (int t = 0; t < 4; ++t) {
                    float e    = sm.c2s[colbase + t] - r2 * acc[i][4 * m + t];
                    int   code = kt * 256 + colbase + t;
                    if (e < bestE[i]) { bestE[i] = e; bestI[i] = code; }
                }
            }
        }
    }

    // ---- argmin reduce across the 16 code-group lanes (tie -> smallest index) ----
    #pragma unroll
    for (int i = 0; i < 4; ++i) {
        float e  = bestE[i];
        int   id = bestI[i];
        #pragma unroll
        for (int off = 8; off > 0; off >>= 1) {
            float oe = __shfl_down_sync(0xffffffffu, e,  off, 16);
            int   oi = __shfl_down_sync(0xffffffffu, id, off, 16);
            if (oe < e || (oe == e && oi < id)) { e = oe; id = oi; }
        }
        if (cg == 0) {
            int v = vg * 4 + i;
            sm.sidx[v] = id;
            bestE[i] = sqrtf(fmaxf(sm.z2s[v] + e, 0.f));   // ||z - q||
        }
    }
    if (cg == 0)
        sm.redsum[vg] = (bestE[0] + bestE[1]) + (bestE[2] + bestE[3]);
    __syncthreads();
    if (tid == 0) {
        float s = 0.f;
        #pragma unroll
        for (int i = 0; i < 16; ++i) s += sm.redsum[i];
        g_partial[blockIdx.x] = s;
    }

    // ---- gather chosen rows into SMEM (coalesced L2 reads), then coalesced store ----
    float* qr = sm.cbs;   // reuse, stride 129 (conflict-free both phases)
    {
        int wrp = tid >> 5, lane = tid & 31;
        #pragma unroll
        for (int vv = 0; vv < 8; ++vv) {
            int v   = wrp * 8 + vv;
            int row = sm.sidx[v];
            const float* cr = codebook + row * CH;
            #pragma unroll
            for (int cc = 0; cc < 4; ++cc) {
                int c = cc * 32 + lane;
                qr[v * 129 + c] = cr[c];
            }
        }
    }
    __syncthreads();
    {
        float* obase = out + (size_t)b * (CH * 4096) + h * 64;
        const int w  = tid & 63;
        const int c0 = tid >> 6;
        #pragma unroll
        for (int it = 0; it < 32; ++it) {
            int c = it * 4 + c0;
            obase[c * 4096 + w] = qr[w * 129 + c];
        }
    }
}

// ---------------------------------------------------------------------------
// Deterministic final reduction of loss partials; writes the two scalars.
// ---------------------------------------------------------------------------
__global__ void finalize_kernel(float* __restrict__ out) {
    __shared__ float s[256];
    int t = threadIdx.x;
    float a = 0.f;
    #pragma unroll
    for (int i = 0; i < 4; ++i) a += g_partial[t + i * 256];
    s[t] = a;
    __syncthreads();
    for (int off = 128; off > 0; off >>= 1) {
        if (t < off) s[t] += s[t + off];
        __syncthreads();
    }
    if (t == 0) {
        float mean = s[0] * (1.0f / 65536.0f);
        out[QELEMS]     = 0.25f * mean;   // loss0
        out[QELEMS + 1] = mean;           // loss1
    }
}

extern "C" void kernel_launch(void* const* d_in, const int* in_sizes, int n_in,
                              void* d_out, int out_size) {
    const float* x        = (const float*)d_in[0];
    const float* codebook = (const float*)d_in[1];
    float*       out      = (float*)d_out;

    prep_kernel<<<CB_K, CH>>>(codebook);

    cudaFuncSetAttribute(vq_main, cudaFuncAttributeMaxDynamicSharedMemorySize,
                         (int)sizeof(Smem));
    vq_main<<<NBLK, 256, sizeof(Smem)>>>(x, codebook, out);

    if (out_size >= QELEMS + 2)
        finalize_kernel<<<1, 256>>>(out);
}

// round 2
// speedup vs baseline: 1.0344x; 1.0344x over previous
#include <cuda_runtime.h>
#include <math.h>

#define CB_K   1024
#define CH     128
#define NVEC   65536
#define QELEMS 8388608
#define NBLK   1024   // NVEC / 64
#define KT     128    // codes per k-tile
#define NKT    (CB_K / KT)   // 8 tiles

// Persistent scratch (no allocations allowed)
__device__ float g_cbT[CB_K * CH];   // tile-major transposed codebook:
                                     // tile t: [c][k_local] contiguous 16384 floats
__device__ float g_c2[CB_K];         // ||codebook[k]||^2
__device__ float g_partial[NBLK];    // per-block loss partial sums

// ---------------- packed fp32x2 helpers (FFMA2 path ptxas won't emit) -------
__device__ __forceinline__ unsigned long long ffma2(unsigned long long a,
                                                    unsigned long long b,
                                                    unsigned long long c) {
    unsigned long long d;
    asm("fma.rn.f32x2 %0, %1, %2, %3;" : "=l"(d) : "l"(a), "l"(b), "l"(c));
    return d;
}
__device__ __forceinline__ unsigned long long splat2(float x) {
    unsigned long long d;
    asm("mov.b64 %0, {%1, %1};" : "=l"(d) : "f"(x));
    return d;
}
__device__ __forceinline__ void unpack2(unsigned long long v, float& lo, float& hi) {
    asm("mov.b64 {%0, %1}, %2;" : "=f"(lo), "=f"(hi) : "l"(v));
}
__device__ __forceinline__ void cp_async16(void* smem_dst, const void* gsrc) {
    unsigned sa = (unsigned)__cvta_generic_to_shared(smem_dst);
    asm volatile("cp.async.cg.shared.global [%0], [%1], 16;" :: "r"(sa), "l"(gsrc));
}

// ---------------------------------------------------------------------------
// Prep: transpose codebook into tile-major [tile][c][k_local] + row norms^2.
// ---------------------------------------------------------------------------
__global__ void prep_kernel(const float* __restrict__ codebook) {
    int k = blockIdx.x;
    int c = threadIdx.x;
    float v = codebook[k * CH + c];
    g_cbT[(k >> 7) * (CH * KT) + c * KT + (k & 127)] = v;
    float s = v * v;
    #pragma unroll
    for (int off = 16; off > 0; off >>= 1)
        s += __shfl_down_sync(0xffffffffu, s, off);
    __shared__ float ws[4];
    if ((c & 31) == 0) ws[c >> 5] = s;
    __syncthreads();
    if (c == 0) g_c2[k] = (ws[0] + ws[1]) + (ws[2] + ws[3]);
}

// ---------------------------------------------------------------------------
// SMEM layout (floats):
//   [0      .. 8192 )  zsT[c][w]   (128 x 64)
//   [8192   .. 9216 )  c2all[1024]
//   [9216   .. 9280 )  rn2[64]
//   [9280   .. 9344 )  z2s[64]
//   [9344   .. 9360 )  redsum[16]
//   [9360   .. 9424 )  sidx[64] (ints)
//   [9472   .. 25856)  buf0 (128 c x 128 codes)
//   [25856  .. 42240)  buf1
// qr[64][129] reuses buf0 after the GEMM loop.
// ---------------------------------------------------------------------------
#define OFF_ZST   0
#define OFF_C2    8192
#define OFF_RN2   9216
#define OFF_Z2    9280
#define OFF_RED   9344
#define OFF_SIDX  9360
#define OFF_BUF0  9472
#define OFF_BUF1  25856
#define SMEM_FLOATS 42240

__global__ void __launch_bounds__(256, 1)
vq_main(const float* __restrict__ x, const float* __restrict__ codebook,
        float* __restrict__ out) {
    extern __shared__ float sf[];

    const int tid = threadIdx.x;
    const int n0  = blockIdx.x * 64;
    const int b   = n0 >> 12;          // n = b*4096 + h*64 + w
    const int h   = (n0 >> 6) & 63;
    const float* xbase = x + (size_t)b * (CH * 4096) + h * 64;

    // ---- kick off prefetch of codebook tile 0 (64KB) ----
    {
        const float4* src = reinterpret_cast<const float4*>(g_cbT);
        float4* dst = reinterpret_cast<float4*>(sf + OFF_BUF0);
        #pragma unroll
        for (int it = 0; it < 16; ++it)
            cp_async16(dst + it * 256 + tid, src + it * 256 + tid);
        asm volatile("cp.async.commit_group;");
    }

    // ---- load + transpose x tile (coalesced along w) ----
    {
        const int w  = tid & 63;
        const int c0 = tid >> 6;
        #pragma unroll
        for (int it = 0; it < 32; ++it) {
            int c = it * 4 + c0;
            sf[OFF_ZST + c * 64 + w] = xbase[c * 4096 + w];
        }
    }
    // ---- preload all c2 ----
    #pragma unroll
    for (int i = 0; i < 4; ++i)
        sf[OFF_C2 + i * 256 + tid] = g_c2[i * 256 + tid];
    __syncthreads();

    // ---- per-vector norms (64 threads, conflict-free column reads) ----
    if (tid < 64) {
        float s0 = 0.f, s1 = 0.f, s2 = 0.f, s3 = 0.f;
        #pragma unroll
        for (int c = 0; c < 128; c += 4) {
            float v0 = sf[OFF_ZST + (c + 0) * 64 + tid];
            float v1 = sf[OFF_ZST + (c + 1) * 64 + tid];
            float v2 = sf[OFF_ZST + (c + 2) * 64 + tid];
            float v3 = sf[OFF_ZST + (c + 3) * 64 + tid];
            s0 = fmaf(v0, v0, s0); s1 = fmaf(v1, v1, s1);
            s2 = fmaf(v2, v2, s2); s3 = fmaf(v3, v3, s3);
        }
        float s   = (s0 + s1) + (s2 + s3);
        float nrm = sqrtf(s);
        float r   = 1.0f / fmaxf(nrm, 1e-12f);
        sf[OFF_RN2 + tid] = 2.0f * r;
        sf[OFF_Z2  + tid] = s * r * r;
    }

    const int vg = tid >> 4;   // 0..15 : vectors 4*vg .. 4*vg+3
    const int cg = tid & 15;   // 0..15 : float4 chunks {cg, cg+16} of the 128-code tile

    float bestE[4];
    int   bestI[4];
    #pragma unroll
    for (int i = 0; i < 4; ++i) { bestE[i] = 3.4e38f; bestI[i] = 0; }

    const float4* zp = reinterpret_cast<const float4*>(sf + OFF_ZST);

    for (int kt = 0; kt < NKT; ++kt) {
        // prefetch next tile into the other buffer (prev compute on it is done:
        // we synced at the end of the previous iteration)
        if (kt + 1 < NKT) {
            const float4* src = reinterpret_cast<const float4*>(
                g_cbT + (kt + 1) * (CH * KT));
            float4* dst = reinterpret_cast<float4*>(
                sf + (((kt + 1) & 1) ? OFF_BUF1 : OFF_BUF0));
            #pragma unroll
            for (int it = 0; it < 16; ++it)
                cp_async16(dst + it * 256 + tid, src + it * 256 + tid);
            asm volatile("cp.async.commit_group;");
            asm volatile("cp.async.wait_group 1;");
        } else {
            asm volatile("cp.async.wait_group 0;");
        }
        __syncthreads();   // tile kt fully visible to all threads

        const float* bufb = sf + ((kt & 1) ? OFF_BUF1 : OFF_BUF0);
        const ulonglong2* cbu = reinterpret_cast<const ulonglong2*>(bufb);

        unsigned long long acc[4][4];   // [vec][code-pair]; pairs: chunk cg (2), chunk cg+16 (2)
        #pragma unroll
        for (int i = 0; i < 4; ++i)
            #pragma unroll
            for (int j = 0; j < 4; ++j) acc[i][j] = 0ull;

        #pragma unroll 8
        for (int c = 0; c < 128; ++c) {
            float4 z = zp[c * 16 + vg];                       // half-warp broadcast
            ulonglong2 qa = cbu[c * 32 + cg];                 // codes 4cg..4cg+3
            ulonglong2 qb = cbu[c * 32 + cg + 16];            // codes 64+4cg..64+4cg+3
            unsigned long long zz0 = splat2(z.x);
            unsigned long long zz1 = splat2(z.y);
            unsigned long long zz2 = splat2(z.z);
            unsigned long long zz3 = splat2(z.w);
            acc[0][0] = ffma2(zz0, qa.x, acc[0][0]);
            acc[0][1] = ffma2(zz0, qa.y, acc[0][1]);
            acc[0][2] = ffma2(zz0, qb.x, acc[0][2]);
            acc[0][3] = ffma2(zz0, qb.y, acc[0][3]);
            acc[1][0] = ffma2(zz1, qa.x, acc[1][0]);
            acc[1][1] = ffma2(zz1, qa.y, acc[1][1]);
            acc[1][2] = ffma2(zz1, qb.x, acc[1][2]);
            acc[1][3] = ffma2(zz1, qb.y, acc[1][3]);
            acc[2][0] = ffma2(zz2, qa.x, acc[2][0]);
            acc[2][1] = ffma2(zz2, qa.y, acc[2][1]);
            acc[2][2] = ffma2(zz2, qb.x, acc[2][2]);
            acc[2][3] = ffma2(zz2, qb.y, acc[2][3]);
            acc[3][0] = ffma2(zz3, qa.x, acc[3][0]);
            acc[3][1] = ffma2(zz3, qa.y, acc[3][1]);
            acc[3][2] = ffma2(zz3, qb.x, acc[3][2]);
            acc[3][3] = ffma2(zz3, qb.y, acc[3][3]);
        }

        // ---- epilogue: e = c2 - rn2*dot, running argmin (ascending code order) ----
        float cv[8];
        int   base0 = cg * 4, base1 = (cg + 16) * 4;
        #pragma unroll
        for (int t = 0; t < 4; ++t) {
            cv[t]     = sf[OFF_C2 + kt * 128 + base0 + t];
            cv[4 + t] = sf[OFF_C2 + kt * 128 + base1 + t];
        }
        #pragma unroll
        for (int i = 0; i < 4; ++i) {
            float r2 = sf[OFF_RN2 + vg * 4 + i];
            #pragma unroll
            for (int j = 0; j < 4; ++j) {
                float lo, hi;
                unpack2(acc[i][j], lo, hi);
                int cb = (j < 2) ? (base0 + (j & 1) * 2) : (base1 + (j & 1) * 2);
                float e0 = fmaf(-r2, lo, cv[(j >> 1) * 4 + (j & 1) * 2 + 0]);
                float e1 = fmaf(-r2, hi, cv[(j >> 1) * 4 + (j & 1) * 2 + 1]);
                int code = kt * 128 + cb;
                if (e0 < bestE[i]) { bestE[i] = e0; bestI[i] = code; }
                if (e1 < bestE[i]) { bestE[i] = e1; bestI[i] = code + 1; }
            }
        }
        __syncthreads();   // done reading this buffer before it is refilled
    }

    // ---- argmin reduce across the 16 code-group lanes (tie -> smallest index) ----
    #pragma unroll
    for (int i = 0; i < 4; ++i) {
        float e  = bestE[i];
        int   id = bestI[i];
        #pragma unroll
        for (int off = 8; off > 0; off >>= 1) {
            float oe = __shfl_down_sync(0xffffffffu, e,  off, 16);
            int   oi = __shfl_down_sync(0xffffffffu, id, off, 16);
            if (oe < e || (oe == e && oi < id)) { e = oe; id = oi; }
        }
        if (cg == 0) {
            int v = vg * 4 + i;
            reinterpret_cast<int*>(sf + OFF_SIDX)[v] = id;
            bestE[i] = sqrtf(fmaxf(sf[OFF_Z2 + v] + e, 0.f));   // ||z - q||
        }
    }
    if (cg == 0)
        sf[OFF_RED + vg] = (bestE[0] + bestE[1]) + (bestE[2] + bestE[3]);
    __syncthreads();
    if (tid == 0) {
        float s = 0.f;
        #pragma unroll
        for (int i = 0; i < 16; ++i) s += sf[OFF_RED + i];
        g_partial[blockIdx.x] = s;
    }

    // ---- gather chosen rows into SMEM (coalesced L2 reads), coalesced store ----
    float* qr = sf + OFF_BUF0;   // [64][129]
    {
        int wrp = tid >> 5, lane = tid & 31;
        const int* sidx = reinterpret_cast<const int*>(sf + OFF_SIDX);
        #pragma unroll
        for (int vv = 0; vv < 8; ++vv) {
            int v   = wrp * 8 + vv;
            int row = sidx[v];
            const float* cr = codebook + row * CH;
            #pragma unroll
            for (int cc = 0; cc < 4; ++cc) {
                int c = cc * 32 + lane;
                qr[v * 129 + c] = cr[c];
            }
        }
    }
    __syncthreads();
    {
        float* obase = out + (size_t)b * (CH * 4096) + h * 64;
        const int w  = tid & 63;
        const int c0 = tid >> 6;
        #pragma unroll
        for (int it = 0; it < 32; ++it) {
            int c = it * 4 + c0;
            obase[c * 4096 + w] = qr[w * 129 + c];
        }
    }
}

// ---------------------------------------------------------------------------
__global__ void finalize_kernel(float* __restrict__ out) {
    __shared__ float s[256];
    int t = threadIdx.x;
    float a = 0.f;
    #pragma unroll
    for (int i = 0; i < 4; ++i) a += g_partial[t + i * 256];
    s[t] = a;
    __syncthreads();
    for (int off = 128; off > 0; off >>= 1) {
        if (t < off) s[t] += s[t + off];
        __syncthreads();
    }
    if (t == 0) {
        float mean = s[0] * (1.0f / 65536.0f);
        out[QELEMS]     = 0.25f * mean;   // loss0
        out[QELEMS + 1] = mean;           // loss1
    }
}

extern "C" void kernel_launch(void* const* d_in, const int* in_sizes, int n_in,
                              void* d_out, int out_size) {
    const float* x        = (const float*)d_in[0];
    const float* codebook = (const float*)d_in[1];
    float*       out      = (float*)d_out;

    prep_kernel<<<CB_K, CH>>>(codebook);

    cudaFuncSetAttribute(vq_main, cudaFuncAttributeMaxDynamicSharedMemorySize,
                         SMEM_FLOATS * 4);
    vq_main<<<NBLK, 256, SMEM_FLOATS * 4>>>(x, codebook, out);

    if (out_size >= QELEMS + 2)
        finalize_kernel<<<1, 256>>>(out);
}